// round 5
// baseline (speedup 1.0000x reference)
#include <cuda_runtime.h>
#include <cuda_bf16.h>
#include <cstdint>

// Shapes (fixed by the problem)
#define B_  32
#define H_  8
#define C_  64
#define L_  1024
#define HC_ 512          // H_*C_
#define K_  6            // int(log(1024)) = 6
#define G_  8            // row-groups per batch in stage-1 reduction
#define RPG_ 64          // rows per group (HC_/G_)

// Scratch (no allocations allowed -> __device__ globals)
__device__ float g_partial[B_ * G_ * L_];   // 1 MB
__device__ float g_meanv[B_ * L_];          // 128 KB  (mean over H,C per (b,l))
__device__ int   g_idx[K_];
__device__ float g_wts[B_ * K_];

// ---------------------------------------------------------------------------
// Kernel 1: partial reduce of corr over 64-row groups.
// grid (B_, G_), 1024 threads; thread = one l column; fully coalesced.
// ---------------------------------------------------------------------------
__global__ void k_partial(const float* __restrict__ corr) {
    const int b = blockIdx.x;
    const int g = blockIdx.y;
    const int l = threadIdx.x;
    const float* base = corr + ((size_t)b * HC_ + (size_t)g * RPG_) * L_ + l;
    float s = 0.f;
#pragma unroll 8
    for (int r = 0; r < RPG_; ++r) s += base[(size_t)r * L_];
    g_partial[((size_t)b * G_ + g) * L_ + l] = s;
}

// ---------------------------------------------------------------------------
// Kernel 2: combine partials -> mean_value[b,l]. grid B_, 1024 threads.
// ---------------------------------------------------------------------------
__global__ void k_combine() {
    const int b = blockIdx.x;
    const int l = threadIdx.x;
    float s = 0.f;
#pragma unroll
    for (int g = 0; g < G_; ++g) s += g_partial[((size_t)b * G_ + g) * L_ + l];
    g_meanv[(size_t)b * L_ + l] = s * (1.0f / (float)HC_);
}

// ---------------------------------------------------------------------------
// Kernel 3: single block. batch-mean, top-6 (argmax iterate, smaller-index
// tie-break), per-batch softmax over selected means. All deterministic.
// ---------------------------------------------------------------------------
__global__ void k_topk_softmax() {
    __shared__ float sm[L_];     // batch-sum of mean_value (ranking only)
    __shared__ float rv[L_];
    __shared__ int   ri[L_];
    __shared__ int   s_idx[K_];

    const int l = threadIdx.x;   // 1024 threads

    float s = 0.f;
#pragma unroll 4
    for (int b = 0; b < B_; ++b) s += g_meanv[(size_t)b * L_ + l];
    sm[l] = s;
    __syncthreads();

    for (int k = 0; k < K_; ++k) {
        rv[l] = sm[l];
        ri[l] = l;
        for (int off = L_ / 2; off > 0; off >>= 1) {
            __syncthreads();
            if (l < off) {
                float v2 = rv[l + off]; int i2 = ri[l + off];
                if (v2 > rv[l] || (v2 == rv[l] && i2 < ri[l])) {
                    rv[l] = v2; ri[l] = i2;
                }
            }
        }
        __syncthreads();
        if (l == 0) {
            s_idx[k]   = ri[0];
            g_idx[k]   = ri[0];
            sm[ri[0]]  = -3.0e38f;   // remove from further consideration
        }
        __syncthreads();
    }

    // Per-batch softmax over mean_value[b, idx[0..5]]
    if (l < B_) {
        const int b = l;
        float w[K_];
        float m = -3.0e38f;
#pragma unroll
        for (int k = 0; k < K_; ++k) {
            w[k] = g_meanv[(size_t)b * L_ + s_idx[k]];
            m = fmaxf(m, w[k]);
        }
        float sum = 0.f;
#pragma unroll
        for (int k = 0; k < K_; ++k) { w[k] = __expf(w[k] - m); sum += w[k]; }
        const float inv = 1.0f / sum;
#pragma unroll
        for (int k = 0; k < K_; ++k) g_wts[b * K_ + k] = w[k] * inv;
    }
}

// ---------------------------------------------------------------------------
// Kernel 4: delays aggregation.
// One block per (b,h,c) row: stage 1024 floats in smem (float4 loads),
// then out[l] = sum_k smem[(l+idx_k)&1023] * w[b,k].
// smem reads are stride-1 per warp (conflict-free); stores coalesced.
// ---------------------------------------------------------------------------
__global__ __launch_bounds__(256) void k_agg(const float* __restrict__ values,
                                             float* __restrict__ out) {
    __shared__ float sv[L_];
    const int row = blockIdx.x;          // 0 .. B*H*C-1
    const int b   = row >> 9;            // row / (H_*C_)
    const int t   = threadIdx.x;         // 256 threads

    // Stage the row (4KB) via float4
    const float4* src = reinterpret_cast<const float4*>(values + (size_t)row * L_);
    reinterpret_cast<float4*>(sv)[t] = src[t];

    // Broadcast weights + indices (L2-resident, 12 scalar loads per block)
    float w0 = g_wts[b * K_ + 0], w1 = g_wts[b * K_ + 1], w2 = g_wts[b * K_ + 2];
    float w3 = g_wts[b * K_ + 3], w4 = g_wts[b * K_ + 4], w5 = g_wts[b * K_ + 5];
    int   i0 = g_idx[0], i1 = g_idx[1], i2 = g_idx[2];
    int   i3 = g_idx[3], i4 = g_idx[4], i5 = g_idx[5];

    __syncthreads();

    float* dst = out + (size_t)row * L_;
#pragma unroll
    for (int j = 0; j < 4; ++j) {
        const int l = t + j * 256;
        float acc;
        acc  = sv[(l + i0) & (L_ - 1)] * w0;
        acc += sv[(l + i1) & (L_ - 1)] * w1;
        acc += sv[(l + i2) & (L_ - 1)] * w2;
        acc += sv[(l + i3) & (L_ - 1)] * w3;
        acc += sv[(l + i4) & (L_ - 1)] * w4;
        acc += sv[(l + i5) & (L_ - 1)] * w5;
        dst[l] = acc;
    }
}

// ---------------------------------------------------------------------------
extern "C" void kernel_launch(void* const* d_in, const int* in_sizes, int n_in,
                              void* d_out, int out_size) {
    const float* values = (const float*)d_in[0];
    const float* corr   = (const float*)d_in[1];
    float*       out    = (float*)d_out;

    dim3 g1(B_, G_);
    k_partial<<<g1, L_>>>(corr);
    k_combine<<<B_, L_>>>();
    k_topk_softmax<<<1, L_>>>();
    k_agg<<<B_ * H_ * C_, 256>>>(values, out);
}

// round 6
// speedup vs baseline: 1.1114x; 1.1114x over previous
#include <cuda_runtime.h>
#include <cuda_bf16.h>
#include <cstdint>

// Shapes (fixed by the problem)
#define B_   32
#define H_   8
#define C_   64
#define L_   1024
#define HC_  512          // H_*C_
#define K_   6            // int(log(1024)) = 6
#define G_   16           // row-groups per batch in stage-1 reduction
#define RPG_ 32           // rows per group (HC_/G_)
#define ROWS_PER_BLK 4    // k_agg rows per block

// Scratch (no allocations allowed -> __device__ globals)
__device__ float g_partial[B_ * G_ * L_];   // 2 MB
__device__ float g_meanv[B_ * L_];          // 128 KB  (mean over H,C per (b,l))
__device__ int   g_idx[K_];
__device__ float g_wts[B_ * K_];

// ---------------------------------------------------------------------------
// Kernel 1: partial reduce of corr over 32-row groups, float4-vectorized.
// grid (B_, G_), 256 threads; thread = one 4-wide l column; fully coalesced.
// ---------------------------------------------------------------------------
__global__ __launch_bounds__(256) void k_partial(const float* __restrict__ corr) {
    const int b = blockIdx.x;
    const int g = blockIdx.y;
    const int t = threadIdx.x;                        // float4 column
    const float4* __restrict__ base =
        reinterpret_cast<const float4*>(corr) +
        ((size_t)b * HC_ + (size_t)g * RPG_) * (L_ / 4) + t;

    float4 a0 = make_float4(0.f, 0.f, 0.f, 0.f);
    float4 a1 = make_float4(0.f, 0.f, 0.f, 0.f);
#pragma unroll 8
    for (int r = 0; r < RPG_; r += 2) {
        float4 v0 = base[(size_t)r * (L_ / 4)];
        float4 v1 = base[(size_t)(r + 1) * (L_ / 4)];
        a0.x += v0.x; a0.y += v0.y; a0.z += v0.z; a0.w += v0.w;
        a1.x += v1.x; a1.y += v1.y; a1.z += v1.z; a1.w += v1.w;
    }
    float4 s;
    s.x = a0.x + a1.x; s.y = a0.y + a1.y; s.z = a0.z + a1.z; s.w = a0.w + a1.w;
    reinterpret_cast<float4*>(g_partial)[((size_t)b * G_ + g) * (L_ / 4) + t] = s;
}

// ---------------------------------------------------------------------------
// Kernel 2: combine partials -> mean_value[b,l]. grid B_, 256 threads, float4.
// ---------------------------------------------------------------------------
__global__ __launch_bounds__(256) void k_combine() {
    const int b = blockIdx.x;
    const int t = threadIdx.x;
    const float4* p4 = reinterpret_cast<const float4*>(g_partial);
    float4 s = make_float4(0.f, 0.f, 0.f, 0.f);
#pragma unroll
    for (int g = 0; g < G_; ++g) {
        float4 v = p4[((size_t)b * G_ + g) * (L_ / 4) + t];
        s.x += v.x; s.y += v.y; s.z += v.z; s.w += v.w;
    }
    const float inv = 1.0f / (float)HC_;
    s.x *= inv; s.y *= inv; s.z *= inv; s.w *= inv;
    reinterpret_cast<float4*>(g_meanv)[(size_t)b * (L_ / 4) + t] = s;
}

// ---------------------------------------------------------------------------
// Kernel 3: single block, 256 threads. batch-mean, top-6 (argmax iterate with
// smaller-index tie-break -> same SET as lax.top_k; order irrelevant since the
// final softmax-weighted sum is permutation invariant), per-batch softmax.
// ---------------------------------------------------------------------------
__global__ __launch_bounds__(256) void k_topk_softmax() {
    __shared__ float sm[L_];
    __shared__ float wval[8];
    __shared__ int   widx[8];
    __shared__ int   s_idx[K_];

    const int t   = threadIdx.x;
    const int wid = t >> 5;
    const int lid = t & 31;

    // column sums of mean_value over b (ranking criterion; /B is monotone)
#pragma unroll
    for (int j = 0; j < 4; ++j) {
        const int l = t + j * 256;
        float s = 0.f;
#pragma unroll 8
        for (int b = 0; b < B_; ++b) s += g_meanv[(size_t)b * L_ + l];
        sm[l] = s;
    }
    __syncthreads();

    for (int k = 0; k < K_; ++k) {
        // local best over this thread's 4 slots (ascending l -> earlier kept on tie)
        float bv = -3.0e38f; int bi = 0x7fffffff;
#pragma unroll
        for (int j = 0; j < 4; ++j) {
            const int l = t + j * 256;
            const float v = sm[l];
            if (v > bv || (v == bv && l < bi)) { bv = v; bi = l; }
        }
        // warp reduce
#pragma unroll
        for (int off = 16; off > 0; off >>= 1) {
            float v2 = __shfl_down_sync(0xffffffffu, bv, off);
            int   i2 = __shfl_down_sync(0xffffffffu, bi, off);
            if (v2 > bv || (v2 == bv && i2 < bi)) { bv = v2; bi = i2; }
        }
        if (lid == 0) { wval[wid] = bv; widx[wid] = bi; }
        __syncthreads();
        if (t == 0) {
            float fv = wval[0]; int fi = widx[0];
#pragma unroll
            for (int w = 1; w < 8; ++w) {
                if (wval[w] > fv || (wval[w] == fv && widx[w] < fi)) {
                    fv = wval[w]; fi = widx[w];
                }
            }
            s_idx[k] = fi;
            g_idx[k] = fi;
            sm[fi]   = -3.0e38f;
        }
        __syncthreads();
    }

    // per-batch softmax over mean_value[b, idx[0..5]]
    if (t < B_) {
        const int b = t;
        float w[K_];
        float m = -3.0e38f;
#pragma unroll
        for (int k = 0; k < K_; ++k) {
            w[k] = g_meanv[(size_t)b * L_ + s_idx[k]];
            m = fmaxf(m, w[k]);
        }
        float sum = 0.f;
#pragma unroll
        for (int k = 0; k < K_; ++k) { w[k] = __expf(w[k] - m); sum += w[k]; }
        const float inv = 1.0f / sum;
#pragma unroll
        for (int k = 0; k < K_; ++k) g_wts[b * K_ + k] = w[k] * inv;
    }
}

// ---------------------------------------------------------------------------
// Kernel 4: delays aggregation, 4 rows per block.
// Stage 16KB via 4 independent LDG.128 per thread (MLP=4), one sync, then
// out[l] = sum_k sv[(l+idx_k)&1023] * w[b,k]. LDS stride-1 across lanes
// (conflict-free, bytes-minimal 24B/output); stores fully coalesced.
// ---------------------------------------------------------------------------
__global__ __launch_bounds__(256) void k_agg(const float* __restrict__ values,
                                             float* __restrict__ out) {
    __shared__ float sv[ROWS_PER_BLK * L_];
    const int t    = threadIdx.x;
    const int row0 = blockIdx.x * ROWS_PER_BLK;      // 4 rows, same batch b
    const int b    = row0 >> 9;                      // row0 / (H_*C_)

    const float4* __restrict__ src =
        reinterpret_cast<const float4*>(values + (size_t)row0 * L_);
    float4* sv4 = reinterpret_cast<float4*>(sv);
#pragma unroll
    for (int j = 0; j < 4; ++j) sv4[t + j * 256] = src[t + j * 256];

    // broadcast weights + indices (L2-resident scalar loads)
    const float w0 = g_wts[b * K_ + 0], w1 = g_wts[b * K_ + 1], w2 = g_wts[b * K_ + 2];
    const float w3 = g_wts[b * K_ + 3], w4 = g_wts[b * K_ + 4], w5 = g_wts[b * K_ + 5];
    const int   i0 = g_idx[0], i1 = g_idx[1], i2 = g_idx[2];
    const int   i3 = g_idx[3], i4 = g_idx[4], i5 = g_idx[5];

    __syncthreads();

    float* dst = out + (size_t)row0 * L_;
#pragma unroll
    for (int r = 0; r < ROWS_PER_BLK; ++r) {
        const float* s = sv + r * L_;
        float* drow = dst + (size_t)r * L_;
#pragma unroll
        for (int j = 0; j < 4; ++j) {
            const int l = t + j * 256;
            float acc;
            acc  = s[(l + i0) & (L_ - 1)] * w0;
            acc += s[(l + i1) & (L_ - 1)] * w1;
            acc += s[(l + i2) & (L_ - 1)] * w2;
            acc += s[(l + i3) & (L_ - 1)] * w3;
            acc += s[(l + i4) & (L_ - 1)] * w4;
            acc += s[(l + i5) & (L_ - 1)] * w5;
            drow[l] = acc;
        }
    }
}

// ---------------------------------------------------------------------------
extern "C" void kernel_launch(void* const* d_in, const int* in_sizes, int n_in,
                              void* d_out, int out_size) {
    const float* values = (const float*)d_in[0];
    const float* corr   = (const float*)d_in[1];
    float*       out    = (float*)d_out;

    dim3 g1(B_, G_);
    k_partial<<<g1, 256>>>(corr);
    k_combine<<<B_, 256>>>();
    k_topk_softmax<<<1, 256>>>();
    k_agg<<<(B_ * H_ * C_) / ROWS_PER_BLK, 256>>>(values, out);
}

// round 7
// speedup vs baseline: 1.1410x; 1.0267x over previous
#include <cuda_runtime.h>
#include <cuda_bf16.h>
#include <cstdint>

// Shapes (fixed by the problem)
#define B_   32
#define H_   8
#define C_   64
#define L_   1024
#define HC_  512          // H_*C_
#define K_   6            // int(log(1024)) = 6
#define G_   32           // row-groups per batch in stage-1 reduction
#define RPG_ 16           // rows per group (HC_/G_)

// k_agg tiling
#define TROWS 4                     // rows per tile
#define NTILES (B_*H_*C_/TROWS)     // 4096 tiles
#define AGG_BLOCKS 1024
#define TPB  (NTILES/AGG_BLOCKS)    // 4 tiles per block

// Scratch (no allocations allowed -> __device__ globals)
__device__ float g_partial[B_ * G_ * L_];   // 4 MB
__device__ float g_meanv[B_ * L_];          // 128 KB
__device__ int   g_idx[K_];
__device__ float g_wts[B_ * K_];

// ---------------------------------------------------------------------------
// cp.async helpers
// ---------------------------------------------------------------------------
__device__ __forceinline__ void cp_async16(void* smem_dst, const void* gmem_src) {
    uint32_t s = (uint32_t)__cvta_generic_to_shared(smem_dst);
    asm volatile("cp.async.cg.shared.global [%0], [%1], 16;\n" :: "r"(s), "l"(gmem_src));
}
__device__ __forceinline__ void cp_commit() {
    asm volatile("cp.async.commit_group;\n" ::: "memory");
}
template <int N>
__device__ __forceinline__ void cp_wait() {
    asm volatile("cp.async.wait_group %0;\n" :: "n"(N) : "memory");
}

// ---------------------------------------------------------------------------
// Kernel 1: partial reduce of corr over 16-row groups, float4, MLP=16.
// grid (B_, G_) = 1024 blocks, 256 threads.
// ---------------------------------------------------------------------------
__global__ __launch_bounds__(256) void k_partial(const float* __restrict__ corr) {
    const int b = blockIdx.x;
    const int g = blockIdx.y;
    const int t = threadIdx.x;
    const float4* __restrict__ base =
        reinterpret_cast<const float4*>(corr) +
        ((size_t)b * HC_ + (size_t)g * RPG_) * (L_ / 4) + t;

    float4 a0 = make_float4(0.f, 0.f, 0.f, 0.f);
    float4 a1 = make_float4(0.f, 0.f, 0.f, 0.f);
#pragma unroll
    for (int r = 0; r < RPG_; r += 2) {
        float4 v0 = base[(size_t)r * (L_ / 4)];
        float4 v1 = base[(size_t)(r + 1) * (L_ / 4)];
        a0.x += v0.x; a0.y += v0.y; a0.z += v0.z; a0.w += v0.w;
        a1.x += v1.x; a1.y += v1.y; a1.z += v1.z; a1.w += v1.w;
    }
    float4 s;
    s.x = a0.x + a1.x; s.y = a0.y + a1.y; s.z = a0.z + a1.z; s.w = a0.w + a1.w;
    reinterpret_cast<float4*>(g_partial)[((size_t)b * G_ + g) * (L_ / 4) + t] = s;
}

// ---------------------------------------------------------------------------
// Kernel 2: combine partials -> mean_value[b,l]. grid (B_,4), 256 threads.
// ---------------------------------------------------------------------------
__global__ __launch_bounds__(256) void k_combine() {
    const int b = blockIdx.x;
    const int l = blockIdx.y * 256 + threadIdx.x;
    float s = 0.f;
#pragma unroll
    for (int g = 0; g < G_; ++g)
        s += g_partial[((size_t)b * G_ + g) * L_ + l];
    g_meanv[(size_t)b * L_ + l] = s * (1.0f / (float)HC_);
}

// ---------------------------------------------------------------------------
// Kernel 3: single block, 256 threads. batch-mean, top-6 (argmax iterate with
// smaller-index tie-break -> same SET as lax.top_k; order irrelevant since the
// final softmax-weighted sum is permutation invariant), per-batch softmax.
// ---------------------------------------------------------------------------
__global__ __launch_bounds__(256) void k_topk_softmax() {
    __shared__ float sm[L_];
    __shared__ float wval[8];
    __shared__ int   widx[8];
    __shared__ int   s_idx[K_];

    const int t   = threadIdx.x;
    const int wid = t >> 5;
    const int lid = t & 31;

#pragma unroll
    for (int j = 0; j < 4; ++j) {
        const int l = t + j * 256;
        float s = 0.f;
#pragma unroll 8
        for (int b = 0; b < B_; ++b) s += g_meanv[(size_t)b * L_ + l];
        sm[l] = s;
    }
    __syncthreads();

    for (int k = 0; k < K_; ++k) {
        float bv = -3.0e38f; int bi = 0x7fffffff;
#pragma unroll
        for (int j = 0; j < 4; ++j) {
            const int l = t + j * 256;
            const float v = sm[l];
            if (v > bv || (v == bv && l < bi)) { bv = v; bi = l; }
        }
#pragma unroll
        for (int off = 16; off > 0; off >>= 1) {
            float v2 = __shfl_down_sync(0xffffffffu, bv, off);
            int   i2 = __shfl_down_sync(0xffffffffu, bi, off);
            if (v2 > bv || (v2 == bv && i2 < bi)) { bv = v2; bi = i2; }
        }
        if (lid == 0) { wval[wid] = bv; widx[wid] = bi; }
        __syncthreads();
        if (t == 0) {
            float fv = wval[0]; int fi = widx[0];
#pragma unroll
            for (int w = 1; w < 8; ++w) {
                if (wval[w] > fv || (wval[w] == fv && widx[w] < fi)) {
                    fv = wval[w]; fi = widx[w];
                }
            }
            s_idx[k] = fi;
            g_idx[k] = fi;
            sm[fi]   = -3.0e38f;
        }
        __syncthreads();
    }

    if (t < B_) {
        const int b = t;
        float w[K_];
        float m = -3.0e38f;
#pragma unroll
        for (int k = 0; k < K_; ++k) {
            w[k] = g_meanv[(size_t)b * L_ + s_idx[k]];
            m = fmaxf(m, w[k]);
        }
        float sum = 0.f;
#pragma unroll
        for (int k = 0; k < K_; ++k) { w[k] = __expf(w[k] - m); sum += w[k]; }
        const float inv = 1.0f / sum;
#pragma unroll
        for (int k = 0; k < K_; ++k) g_wts[b * K_ + k] = w[k] * inv;
    }
}

// ---------------------------------------------------------------------------
// Kernel 4: delays aggregation, persistent blocks with cp.async double-buffer.
// 1024 blocks x 4 tiles; tile = 4 rows (16KB). While computing tile n from
// buffer n&1, tile n+1 streams into buffer (n+1)&1 via cp.async (no LDG
// round-trip, DRAM latency hidden inside the block).
// ---------------------------------------------------------------------------
__global__ __launch_bounds__(256) void k_agg(const float* __restrict__ values,
                                             float* __restrict__ out) {
    __shared__ float sv[2][TROWS * L_];
    const int t = threadIdx.x;

    // prefetch tile 0
    {
        const int tile0 = blockIdx.x * TPB;
        const float4* src = reinterpret_cast<const float4*>(values + (size_t)tile0 * TROWS * L_);
        float4* dstb = reinterpret_cast<float4*>(sv[0]);
#pragma unroll
        for (int j = 0; j < 4; ++j)
            cp_async16(&dstb[t + j * 256], &src[t + j * 256]);
        cp_commit();
    }

#pragma unroll
    for (int it = 0; it < TPB; ++it) {
        const int tile = blockIdx.x * TPB + it;
        const int row0 = tile * TROWS;
        const int b    = row0 >> 9;

        // prefetch next tile into the other buffer
        if (it + 1 < TPB) {
            const float4* src =
                reinterpret_cast<const float4*>(values + (size_t)(row0 + TROWS) * L_);
            float4* dstb = reinterpret_cast<float4*>(sv[(it + 1) & 1]);
#pragma unroll
            for (int j = 0; j < 4; ++j)
                cp_async16(&dstb[t + j * 256], &src[t + j * 256]);
            cp_commit();
        }

        // broadcast weights + indices (L2-resident) while copies fly
        const float w0 = g_wts[b * K_ + 0], w1 = g_wts[b * K_ + 1], w2 = g_wts[b * K_ + 2];
        const float w3 = g_wts[b * K_ + 3], w4 = g_wts[b * K_ + 4], w5 = g_wts[b * K_ + 5];
        const int   i0 = g_idx[0], i1 = g_idx[1], i2 = g_idx[2];
        const int   i3 = g_idx[3], i4 = g_idx[4], i5 = g_idx[5];

        // wait for current tile's group (1 group still in flight = the prefetch)
        if (it + 1 < TPB) cp_wait<1>(); else cp_wait<0>();
        __syncthreads();

        const float* svc = sv[it & 1];
        float* dst = out + (size_t)row0 * L_;
#pragma unroll
        for (int r = 0; r < TROWS; ++r) {
            const float* s = svc + r * L_;
            float* drow = dst + (size_t)r * L_;
#pragma unroll
            for (int j = 0; j < 4; ++j) {
                const int l = t + j * 256;
                float acc;
                acc  = s[(l + i0) & (L_ - 1)] * w0;
                acc += s[(l + i1) & (L_ - 1)] * w1;
                acc += s[(l + i2) & (L_ - 1)] * w2;
                acc += s[(l + i3) & (L_ - 1)] * w3;
                acc += s[(l + i4) & (L_ - 1)] * w4;
                acc += s[(l + i5) & (L_ - 1)] * w5;
                drow[l] = acc;
            }
        }
        __syncthreads();   // buffer it&1 free before it gets re-prefetched
    }
}

// ---------------------------------------------------------------------------
extern "C" void kernel_launch(void* const* d_in, const int* in_sizes, int n_in,
                              void* d_out, int out_size) {
    const float* values = (const float*)d_in[0];
    const float* corr   = (const float*)d_in[1];
    float*       out    = (float*)d_out;

    dim3 g1(B_, G_);
    k_partial<<<g1, 256>>>(corr);
    dim3 g2(B_, 4);
    k_combine<<<g2, 256>>>();
    k_topk_softmax<<<1, 256>>>();
    k_agg<<<AGG_BLOCKS, 256>>>(values, out);
}